// round 6
// baseline (speedup 1.0000x reference)
#include <cuda_runtime.h>
#include <cuda_bf16.h>
#include <cuda_fp16.h>
#include <cstdint>

#define NN 50000
#define EE 800000
#define DD 128
#define TILES ((NN + 127) / 128)       // 391
#define CSR_BLOCKS ((EE + 255) / 256)  // 3125
#define SCALE_BLOCKS ((NN * 32 + 255) / 256)
#define ASTRIDE 132                    // smem row stride in floats
#define SMEM_BYTES (128 * ASTRIDE * 4) // 67584

// ---------------- scratch (static device globals; no allocation) ----------
// INVARIANT: g_deg and g_cur are all-zero at entry of every kernel_launch
// (zero-initialized at load; re-zeroed by k_fused layer 0 each call).
__device__ __half   g_y16[NN * DD];     // y0 = dinv .* x   (fp16)
__device__ __half   g_h16[NN * DD];     // y1 = dinv .* relu(layer0) (fp16)
__device__ int      g_csr_src[EE];
__device__ int      g_deg[NN];
__device__ int      g_off[NN + 1];
__device__ int      g_cur[NN];
__device__ float    g_dinv[NN];
__device__ int      g_is64;
// W packed in mma.m16n8k16 B-fragment order, bf16 hi/lo
__device__ uint32_t g_bp_hi[2 * 8 * 16 * 64];
__device__ uint32_t g_bp_lo[2 * 8 * 16 * 64];

// ------------- K1: fused dtype-detect + W pack + degree count --------------
__global__ void k_pre_deg(const int* __restrict__ raw,
                          const float* __restrict__ W) {
    __shared__ int found;
    if (threadIdx.x == 0) found = 0;
    __syncthreads();
    // local is64 detection: odd 32-bit words of first 128 int64 values are 0;
    // for int32 input these words are 128 random indices (never all zero).
    if (threadIdx.x < 128) {
        if (raw[2 * threadIdx.x + 1] != 0) found = 1;  // benign race
    }
    __syncthreads();
    int is64 = found ? 0 : 1;
    if (blockIdx.x == 0 && threadIdx.x == 0) g_is64 = is64;

    int idx = blockIdx.x * blockDim.x + threadIdx.x;
    // W pack (blocks 0..127)
    if (idx < 2 * DD * DD) {
        int l = idx >> 14;
        int r = idx & 16383;
        int k = r >> 7;    // K index (in-dim)
        int n = r & 127;   // N index (out-dim)
        float v = W[l * DD * DD + k * DD + n];
        __nv_bfloat16 h  = __float2bfloat16(v);
        __nv_bfloat16 lo = __float2bfloat16(v - __bfloat162float(h));
        int ks = k >> 4, kk = k & 15;
        int reg = kk >> 3, k8 = kk & 7;
        int lane = ((n & 7) << 2) | (k8 >> 1);
        int i    = k8 & 1;
        int nt   = n >> 3;
        size_t u32i = ((((size_t)l * 8 + ks) * 16 + nt) * 64) + (size_t)lane * 2 + reg;
        ((unsigned short*)g_bp_hi)[u32i * 2 + i] = __bfloat16_as_ushort(h);
        ((unsigned short*)g_bp_lo)[u32i * 2 + i] = __bfloat16_as_ushort(lo);
    }
    // degree count (g_deg zero by invariant)
    if (idx < EE) {
        int d;
        if (is64) d = (int)((const long long*)raw)[EE + idx];
        else      d = ((const int*)raw)[EE + idx];
        atomicAdd(&g_deg[d], 1);
    }
}

// ------------- K2: single-block scan -> offsets + dinv ---------------------
__global__ void k_scan() {
    const int T = 1024;
    const int ITEMS = (NN + T - 1) / T;  // 49
    __shared__ int sm[T];
    int t = threadIdx.x;
    int base = t * ITEMS;
    int sum = 0;
    for (int j = 0; j < ITEMS; ++j) {
        int idx = base + j;
        if (idx < NN) sum += g_deg[idx];
    }
    sm[t] = sum;
    __syncthreads();
    for (int dstep = 1; dstep < T; dstep <<= 1) {
        int v = (t >= dstep) ? sm[t - dstep] : 0;
        __syncthreads();
        sm[t] += v;
        __syncthreads();
    }
    int run = sm[t] - sum;
    for (int j = 0; j < ITEMS; ++j) {
        int idx = base + j;
        if (idx < NN) {
            int dg = g_deg[idx];
            g_off[idx] = run;
            g_dinv[idx] = rsqrtf((float)dg + 1.0f);
            run += dg;
        }
    }
    if (t == T - 1) g_off[NN] = sm[T - 1];
}

// ------------- K3: CSR scatter (src only) + y0 = fp16(dinv.*x) -------------
__global__ void k_csr_scale(const void* __restrict__ raw,
                            const float* __restrict__ x) {
    int b = blockIdx.x;
    if (b < CSR_BLOCKS) {
        int e = b * 256 + threadIdx.x;
        if (e < EE) {
            int s, d;
            if (g_is64) {
                const long long* p = (const long long*)raw;
                s = (int)p[e];
                d = (int)p[EE + e];
            } else {
                const int* p = (const int*)raw;
                s = p[e];
                d = p[EE + e];
            }
            int pidx = g_off[d] + atomicAdd(&g_cur[d], 1);
            g_csr_src[pidx] = s;
        }
    } else {
        int i = (b - CSR_BLOCKS) * 256 + threadIdx.x;
        if (i < NN * 32) {
            int row = i >> 5, l = i & 31;
            float di = g_dinv[row];
            float4 v = ((const float4*)(x + (size_t)row * DD))[l];
            __half2 h01 = __floats2half2_rn(v.x * di, v.y * di);
            __half2 h23 = __floats2half2_rn(v.z * di, v.w * di);
            uint2 o;
            o.x = *(uint32_t*)&h01;
            o.y = *(uint32_t*)&h23;
            *(uint2*)(g_y16 + (size_t)row * DD + 4 * l) = o;
        }
    }
}

// ------------- fused agg + GEMM per layer ----------------------------------
__device__ __forceinline__ void mma16816(float* d, const uint32_t* a,
                                         const uint32_t b0, const uint32_t b1) {
    asm volatile(
        "mma.sync.aligned.m16n8k16.row.col.f32.bf16.bf16.f32 "
        "{%0,%1,%2,%3}, {%4,%5,%6,%7}, {%8,%9}, {%0,%1,%2,%3};"
        : "+f"(d[0]), "+f"(d[1]), "+f"(d[2]), "+f"(d[3])
        : "r"(a[0]), "r"(a[1]), "r"(a[2]), "r"(a[3]), "r"(b0), "r"(b1));
}
__device__ __forceinline__ uint32_t pack_hi(float2 v) {
    __nv_bfloat162 h = __floats2bfloat162_rn(v.x, v.y);
    return *(uint32_t*)&h;
}
__device__ __forceinline__ uint32_t pack_lo(float2 v) {
    __nv_bfloat16 h0 = __float2bfloat16(v.x);
    __nv_bfloat16 h1 = __float2bfloat16(v.y);
    __nv_bfloat162 l = __floats2bfloat162_rn(v.x - __bfloat162float(h0),
                                             v.y - __bfloat162float(h1));
    return *(uint32_t*)&l;
}

__global__ void __launch_bounds__(512, 2)
k_fused(const float* __restrict__ bg, float* __restrict__ outext, int layer) {
    extern __shared__ float sA[];   // [128][ASTRIDE]
    int tid  = threadIdx.x;
    int lane = tid & 31;
    int wid  = tid >> 5;            // 0..15
    int nodeBase = blockIdx.x * 128;
    const __half* __restrict__ y = layer ? g_h16 : g_y16;

    // layer 0: restore the zero-invariant on g_deg / g_cur (unused from here on)
    if (layer == 0) {
        int zi = blockIdx.x * 512 + tid;
        // 391*512 = 200192 >= NN
        if (zi < NN) { g_deg[zi] = 0; g_cur[zi] = 0; }
    }

    // ---- phase 1: aggregation, 16 warps x 8 nodes -> smem fp32 ----
    #pragma unroll 1
    for (int i = 0; i < 8; ++i) {
        int r = wid * 8 + i;            // 0..127
        int node = nodeBase + r;
        float4 acc = make_float4(0.f, 0.f, 0.f, 0.f);
        if (node < NN) {
            uint2 v = *(const uint2*)(y + (size_t)node * DD + 4 * lane);
            float2 f01 = __half22float2(*(__half2*)&v.x);
            float2 f23 = __half22float2(*(__half2*)&v.y);
            acc = make_float4(f01.x, f01.y, f23.x, f23.y);
            int beg = g_off[node];
            int end = g_off[node + 1];
            for (int e0 = beg; e0 < end; e0 += 32) {
                int m = end - e0;
                if (m > 32) m = 32;
                int s_all = (lane < m) ? g_csr_src[e0 + lane] : 0;
                int jb = 0;
                for (; jb + 8 <= m; jb += 8) {
                    uint2 vv[8];
                    #pragma unroll
                    for (int j = 0; j < 8; ++j) {
                        int sj = __shfl_sync(0xffffffffu, s_all, jb + j);
                        vv[j] = *(const uint2*)(y + (size_t)sj * DD + 4 * lane);
                    }
                    #pragma unroll
                    for (int j = 0; j < 8; ++j) {
                        float2 a01 = __half22float2(*(__half2*)&vv[j].x);
                        float2 a23 = __half22float2(*(__half2*)&vv[j].y);
                        acc.x += a01.x; acc.y += a01.y;
                        acc.z += a23.x; acc.w += a23.y;
                    }
                }
                for (; jb < m; ++jb) {
                    int sj = __shfl_sync(0xffffffffu, s_all, jb);
                    uint2 vv = *(const uint2*)(y + (size_t)sj * DD + 4 * lane);
                    float2 a01 = __half22float2(*(__half2*)&vv.x);
                    float2 a23 = __half22float2(*(__half2*)&vv.y);
                    acc.x += a01.x; acc.y += a01.y;
                    acc.z += a23.x; acc.w += a23.y;
                }
            }
            float di = g_dinv[node];
            acc.x *= di; acc.y *= di; acc.z *= di; acc.w *= di;
        }
        *(float4*)&sA[r * ASTRIDE + lane * 4] = acc;
    }
    __syncthreads();

    // ---- phase 2: GEMM, warp = 16 rows x 64 cols ----
    int mb    = (wid & 7) * 16;
    int nbase = (wid >> 3) * 64;
    int qrow = lane >> 2;
    int qcol = (lane & 3) * 2;

    float acc[8][4];
    #pragma unroll
    for (int nt = 0; nt < 8; ++nt)
        #pragma unroll
        for (int j = 0; j < 4; ++j) acc[nt][j] = 0.0f;

    const uint2* __restrict__ bhiP = (const uint2*)g_bp_hi;
    const uint2* __restrict__ bloP = (const uint2*)g_bp_lo;

    #pragma unroll 1
    for (int ks = 0; ks < 8; ++ks) {
        int c = ks * 16 + qcol;
        int r0 = mb + qrow;
        int r1 = r0 + 8;
        float2 x0 = *(float2*)&sA[r0 * ASTRIDE + c];
        float2 x1 = *(float2*)&sA[r1 * ASTRIDE + c];
        float2 x2 = *(float2*)&sA[r0 * ASTRIDE + c + 8];
        float2 x3 = *(float2*)&sA[r1 * ASTRIDE + c + 8];
        uint32_t ahi[4], alo[4];
        ahi[0] = pack_hi(x0); alo[0] = pack_lo(x0);
        ahi[1] = pack_hi(x1); alo[1] = pack_lo(x1);
        ahi[2] = pack_hi(x2); alo[2] = pack_lo(x2);
        ahi[3] = pack_hi(x3); alo[3] = pack_lo(x3);

        int bbase = (((layer * 8 + ks) * 16 + (nbase >> 3)) * 32) + lane;
        #pragma unroll
        for (int nt = 0; nt < 8; ++nt) {
            uint2 bh = bhiP[bbase + nt * 32];
            uint2 bl = bloP[bbase + nt * 32];
            mma16816(acc[nt], ahi, bh.x, bh.y);
            mma16816(acc[nt], alo, bh.x, bh.y);
            mma16816(acc[nt], ahi, bl.x, bl.y);
        }
    }

    // ---- epilogue ----
    int gr0 = nodeBase + mb + qrow;
    int gr1 = gr0 + 8;
    if (layer == 0) {
        float d0 = (gr0 < NN) ? g_dinv[gr0] : 0.0f;
        float d1 = (gr1 < NN) ? g_dinv[gr1] : 0.0f;
        #pragma unroll
        for (int nt = 0; nt < 8; ++nt) {
            int col = nbase + nt * 8 + qcol;
            float2 bb = *(const float2*)(bg + col);
            if (gr0 < NN) {
                __half2 o = __floats2half2_rn(
                    fmaxf(acc[nt][0] + bb.x, 0.0f) * d0,
                    fmaxf(acc[nt][1] + bb.y, 0.0f) * d0);
                *(__half2*)(g_h16 + (size_t)gr0 * DD + col) = o;
            }
            if (gr1 < NN) {
                __half2 o = __floats2half2_rn(
                    fmaxf(acc[nt][2] + bb.x, 0.0f) * d1,
                    fmaxf(acc[nt][3] + bb.y, 0.0f) * d1);
                *(__half2*)(g_h16 + (size_t)gr1 * DD + col) = o;
            }
        }
    } else {
        #pragma unroll
        for (int nt = 0; nt < 8; ++nt) {
            int col = nbase + nt * 8 + qcol;
            float2 bb = *(const float2*)(bg + col);
            if (gr0 < NN) {
                float2 o;
                o.x = fmaxf(acc[nt][0] + bb.x, 0.0f);
                o.y = fmaxf(acc[nt][1] + bb.y, 0.0f);
                *(float2*)(outext + (size_t)gr0 * DD + col) = o;
            }
            if (gr1 < NN) {
                float2 o;
                o.x = fmaxf(acc[nt][2] + bb.x, 0.0f);
                o.y = fmaxf(acc[nt][3] + bb.y, 0.0f);
                *(float2*)(outext + (size_t)gr1 * DD + col) = o;
            }
        }
    }
}

// ---------------- launch ----------------------------------------------------
extern "C" void kernel_launch(void* const* d_in, const int* in_sizes, int n_in,
                              void* d_out, int out_size) {
    const float* x  = (const float*)d_in[0];
    const void*  ei = d_in[1];
    const float* W  = (const float*)d_in[2];
    const float* b  = (const float*)d_in[3];
    float* out = (float*)d_out;

    cudaFuncSetAttribute(k_fused, cudaFuncAttributeMaxDynamicSharedMemorySize,
                         SMEM_BYTES);

    k_pre_deg<<<CSR_BLOCKS, 256>>>((const int*)ei, W);
    k_scan<<<1, 1024>>>();
    k_csr_scale<<<CSR_BLOCKS + SCALE_BLOCKS, 256>>>(ei, x);
    k_fused<<<TILES, 512, SMEM_BYTES>>>(b, out, 0);
    k_fused<<<TILES, 512, SMEM_BYTES>>>(b + DD, out, 1);
}